// round 4
// baseline (speedup 1.0000x reference)
#include <cuda_runtime.h>
#include <cuda_bf16.h>
#include <math.h>

// ---------------- problem constants ----------------
#define EMB   620
#define ECH   1000
#define A2    2000      // 2*ECH
#define H     1000      // DCH
#define V     30000
#define S     50
#define T     50
#define B     32
#define KX    3620      // EMB + H + A2
#define NSTEP (T-1)     // 49
#define NPRED (NSTEP*B) // 1568

#define PRED_ELEMS  ((size_t)T*B*V)       // 48,000,000
#define HID_OFF     PRED_ELEMS
#define ATT_OFF     (PRED_ELEMS + (size_t)B*H)

// ---------------- device scratch (static, no allocation) ----------------
__device__ float g_WhT[ECH * H];            // [k=1000][m=1000]
__device__ float g_WcT[(H + A2) * H];       // [k=3000][m=1000]
__device__ float g_WpT[(size_t)KX * V];     // [k=3620][m=30000]
__device__ float g_WgT[(size_t)KX * 4000];  // [k=3620][row=4000]
__device__ float g_bg[4000];
__device__ float g_annproj[S * B * H];      // [s*32+b][j]
__device__ float g_h[2][B * H];
__device__ float g_hproj[B * H];
__device__ float g_attn[S * B];
__device__ float g_X[(size_t)NSTEP * B * KX];
__device__ float g_gates[B * 4000];         // [b][row]

// ---------------- generic transpose: out[c*R + r] = in[r*C + c] ----------------
__global__ void transpose_kernel(const float* __restrict__ in, float* __restrict__ out,
                                 int R, int C) {
    __shared__ float tile[32][33];
    int c0 = blockIdx.x * 32, r0 = blockIdx.y * 32;
    int tx = threadIdx.x, ty = threadIdx.y;   // (32, 8)
    #pragma unroll
    for (int i = 0; i < 32; i += 8) {
        int r = r0 + ty + i, c = c0 + tx;
        tile[ty + i][tx] = (r < R && c < C) ? in[(size_t)r * C + c] : 0.f;
    }
    __syncthreads();
    #pragma unroll
    for (int i = 0; i < 32; i += 8) {
        int c = c0 + ty + i, r = r0 + tx;
        if (r < R && c < C) out[(size_t)c * R + r] = tile[tx][ty + i];
    }
}

// ---------------- build fused GRU weight (transposed) + bias ----------------
// rows 0..999   : r gate  (W_ih rows 0..999 fused with W_hh rows 0..999)
// rows 1000..1999: z gate (W_ih rows 1000.. fused with W_hh rows 1000..)
// rows 2000..2999: inn    (W_ih rows 2000.., zero on h-columns)
// rows 3000..3999: hn     (W_hh rows 2000.., zero elsewhere)
// column layout matches X = [emb(620), h(1000), ctx(2000)]
__global__ void build_wg_kernel(const float* __restrict__ W_ih,
                                const float* __restrict__ W_hh,
                                float* __restrict__ WgT) {
    size_t idx = (size_t)blockIdx.x * blockDim.x + threadIdx.x;
    size_t total = (size_t)KX * 4000;
    if (idx >= total) return;
    int row = (int)(idx % 4000);
    int k   = (int)(idx / 4000);
    float v = 0.f;
    if (row < 2000) {
        if (k < EMB)              v = W_ih[(size_t)row * 2620 + k];
        else if (k < EMB + H)     v = W_hh[(size_t)row * H + (k - EMB)];
        else                      v = W_ih[(size_t)row * 2620 + (k - H)];
    } else if (row < 3000) {
        if (k < EMB)              v = W_ih[(size_t)row * 2620 + k];
        else if (k >= EMB + H)    v = W_ih[(size_t)row * 2620 + (k - H)];
    } else {
        if (k >= EMB && k < EMB + H) v = W_hh[(size_t)(row - 1000) * H + (k - EMB)];
    }
    WgT[(size_t)k * 4000 + row] = v;
}

__global__ void build_bg_kernel(const float* __restrict__ b_ih,
                                const float* __restrict__ b_hh,
                                float* __restrict__ bg) {
    int r = blockIdx.x * blockDim.x + threadIdx.x;
    if (r >= 4000) return;
    float v;
    if (r < 2000)      v = b_ih[r] + b_hh[r];
    else if (r < 3000) v = b_ih[r];
    else               v = b_hh[r - 1000];
    bg[r] = v;
}

// ---------------- generic tiled GEMM ----------------
// C[m*cm + n*cn] = act( sum_k AT[k*ldA + m] * X[n*ldX + k] + bias[m] )
// BM=64, BN=32, BK=32, 128 threads, 4x4 microtile.
__global__ void __launch_bounds__(128)
gemm_kernel(const float* __restrict__ AT, const float* __restrict__ Xp,
            const float* __restrict__ bias, float* __restrict__ C,
            long long cm, long long cn, int M, int N, int K,
            int ldA, int ldX, int act) {
    __shared__ float Ws[32][64];
    __shared__ float Xs[32][33];
    int bm = blockIdx.x * 64, bn = blockIdx.y * 32;
    int tid = threadIdx.x;
    int tm = tid >> 3;          // 0..15 -> m = bm + tm*4
    int tn = tid & 7;           // 0..7  -> n = bn + tn*4
    float acc[4][4];
    #pragma unroll
    for (int i = 0; i < 4; i++)
        #pragma unroll
        for (int j = 0; j < 4; j++) acc[i][j] = 0.f;

    int a_m  = tid & 63;        // 0..63
    int a_k0 = tid >> 6;        // 0..1
    int x_k  = tid & 31;        // 0..31
    int x_n0 = tid >> 5;        // 0..3

    for (int k0 = 0; k0 < K; k0 += 32) {
        // A tile: Ws[kk][mm] = AT[(k0+kk)*ldA + bm+mm]
        #pragma unroll
        for (int p = 0; p < 16; p++) {
            int kk = p * 2 + a_k0;
            int m  = bm + a_m;
            int kg = k0 + kk;
            Ws[kk][a_m] = (kg < K && m < M) ? AT[(size_t)kg * ldA + m] : 0.f;
        }
        // X tile: Xs[kk][nn] = X[(bn+nn)*ldX + k0+kk]
        #pragma unroll
        for (int p = 0; p < 8; p++) {
            int nn = p * 4 + x_n0;
            int n  = bn + nn;
            int kg = k0 + x_k;
            Xs[x_k][nn] = (n < N && kg < K) ? Xp[(size_t)n * ldX + kg] : 0.f;
        }
        __syncthreads();
        #pragma unroll
        for (int kk = 0; kk < 32; kk++) {
            float4 wv = *reinterpret_cast<const float4*>(&Ws[kk][tm * 4]);
            float x0 = Xs[kk][tn * 4 + 0];
            float x1 = Xs[kk][tn * 4 + 1];
            float x2 = Xs[kk][tn * 4 + 2];
            float x3 = Xs[kk][tn * 4 + 3];
            acc[0][0] += wv.x * x0; acc[0][1] += wv.x * x1; acc[0][2] += wv.x * x2; acc[0][3] += wv.x * x3;
            acc[1][0] += wv.y * x0; acc[1][1] += wv.y * x1; acc[1][2] += wv.y * x2; acc[1][3] += wv.y * x3;
            acc[2][0] += wv.z * x0; acc[2][1] += wv.z * x1; acc[2][2] += wv.z * x2; acc[2][3] += wv.z * x3;
            acc[3][0] += wv.w * x0; acc[3][1] += wv.w * x1; acc[3][2] += wv.w * x2; acc[3][3] += wv.w * x3;
        }
        __syncthreads();
    }
    #pragma unroll
    for (int i = 0; i < 4; i++) {
        int m = bm + tm * 4 + i;
        if (m >= M) continue;
        float bb = bias ? bias[m] : 0.f;
        #pragma unroll
        for (int j = 0; j < 4; j++) {
            int n = bn + tn * 4 + j;
            if (n >= N) continue;
            float v = acc[i][j] + bb;
            if (act == 1) v = tanhf(v);
            C[(long long)m * cm + (long long)n * cn] = v;
        }
    }
}

// ---------------- attention scores + softmax over batch (axis=1) ----------------
__global__ void scores_softmax_kernel(const float* __restrict__ hproj,
                                      const float* __restrict__ annproj,
                                      const float* __restrict__ w_a,
                                      float* __restrict__ attn,
                                      float* __restrict__ attns_out) {
    int s = blockIdx.x;             // 0..49
    int warp = threadIdx.x >> 5;
    int lane = threadIdx.x & 31;
    __shared__ float sm_scores[B];
    for (int it = 0; it < 4; it++) {
        int b = warp + it * 8;
        const float* ap = annproj + (size_t)(s * B + b) * H;
        const float* hp = hproj + (size_t)b * H;
        float sum = 0.f;
        for (int j = lane; j < H; j += 32)
            sum += tanhf(hp[j] + ap[j]) * w_a[j];
        #pragma unroll
        for (int o = 16; o > 0; o >>= 1) sum += __shfl_down_sync(0xffffffffu, sum, o);
        if (lane == 0) sm_scores[b] = sum;
    }
    __syncthreads();
    if (warp == 0) {
        float x = sm_scores[lane];
        float mx = x;
        #pragma unroll
        for (int o = 16; o > 0; o >>= 1) mx = fmaxf(mx, __shfl_xor_sync(0xffffffffu, mx, o));
        float e = expf(x - mx);
        float sum = e;
        #pragma unroll
        for (int o = 16; o > 0; o >>= 1) sum += __shfl_xor_sync(0xffffffffu, sum, o);
        float a = e / sum;
        attn[s * B + lane] = a;
        attns_out[s * B + lane] = a;
    }
}

// ---------------- build X slice: [emb(620), h_prev(1000), ctx(2000)] ----------------
__global__ void build_x_kernel(const int* __restrict__ tokens_t,     // tokens[t-1] base
                               const float* __restrict__ emb,
                               const float* __restrict__ h_prev,
                               const float* __restrict__ attn,
                               const float* __restrict__ ann,
                               float* __restrict__ Xslice) {
    int idx = blockIdx.x * blockDim.x + threadIdx.x;
    if (idx >= B * KX) return;
    int b = idx / KX;
    int e = idx % KX;
    float v;
    if (e < EMB) {
        int tok = tokens_t[b];
        v = emb[(size_t)tok * EMB + e];
    } else if (e < EMB + H) {
        v = h_prev[b * H + (e - EMB)];
    } else {
        int c = e - (EMB + H);
        float sum = 0.f;
        #pragma unroll 5
        for (int s = 0; s < S; s++)
            sum += attn[s * B + b] * ann[(size_t)(s * B + b) * A2 + c];
        v = sum;
    }
    Xslice[(size_t)b * KX + e] = v;
}

// ---------------- GRU combine ----------------
__global__ void gru_combine_kernel(const float* __restrict__ gates,   // [b][4000]
                                   const float* __restrict__ h_old,
                                   float* __restrict__ h_new,
                                   float* __restrict__ hid_out) {
    int idx = blockIdx.x * blockDim.x + threadIdx.x;
    if (idx >= B * H) return;
    int b = idx / H, j = idx % H;
    const float* g = gates + (size_t)b * 4000;
    float r  = 1.f / (1.f + expf(-g[j]));
    float z  = 1.f / (1.f + expf(-g[1000 + j]));
    float nn = tanhf(g[2000 + j] + r * g[3000 + j]);
    float hv = (1.f - z) * nn + z * h_old[idx];
    h_new[idx] = hv;
    if (hid_out) hid_out[idx] = hv;
}

// ---------------- zero preds[0] and attns[0] ----------------
__global__ void zero_kernel(float* __restrict__ out) {
    size_t idx = (size_t)blockIdx.x * blockDim.x + threadIdx.x;
    size_t n0 = (size_t)B * V;
    if (idx < n0) out[idx] = 0.f;
    else if (idx < n0 + S * B) out[ATT_OFF + (idx - n0)] = 0.f;
}

// ---------------- log-softmax in place, one block per (t,b) row ----------------
__global__ void logsoftmax_kernel(float* __restrict__ preds_base) {
    int row = blockIdx.x;            // 0..NPRED-1
    float* p = preds_base + (size_t)row * V;
    int tid = threadIdx.x;
    __shared__ float red[8];
    // max
    float mx = -1e30f;
    for (int i = tid; i < V; i += 256) mx = fmaxf(mx, p[i]);
    #pragma unroll
    for (int o = 16; o > 0; o >>= 1) mx = fmaxf(mx, __shfl_xor_sync(0xffffffffu, mx, o));
    if ((tid & 31) == 0) red[tid >> 5] = mx;
    __syncthreads();
    if (tid < 8) {
        float v = red[tid];
        #pragma unroll
        for (int o = 4; o > 0; o >>= 1) v = fmaxf(v, __shfl_xor_sync(0xffu, v, o));
        red[tid] = v;
    }
    __syncthreads();
    mx = red[0];
    __syncthreads();
    // sum exp
    float sum = 0.f;
    for (int i = tid; i < V; i += 256) sum += expf(p[i] - mx);
    #pragma unroll
    for (int o = 16; o > 0; o >>= 1) sum += __shfl_xor_sync(0xffffffffu, sum, o);
    if ((tid & 31) == 0) red[tid >> 5] = sum;
    __syncthreads();
    if (tid < 8) {
        float v = red[tid];
        #pragma unroll
        for (int o = 4; o > 0; o >>= 1) v += __shfl_xor_sync(0xffu, v, o);
        red[tid] = v;
    }
    __syncthreads();
    float lse = mx + logf(red[0]);
    for (int i = tid; i < V; i += 256) p[i] = p[i] - lse;
}

// ---------------- host orchestration ----------------
static inline int ceil_div(int a, int b) { return (a + b - 1) / b; }

extern "C" void kernel_launch(void* const* d_in, const int* in_sizes, int n_in,
                              void* d_out, int out_size) {
    const int*   tokens = (const int*)  d_in[0];
    const float* ann    = (const float*)d_in[1];
    const float* emb    = (const float*)d_in[2];
    const float* W_h    = (const float*)d_in[3];
    const float* b_h    = (const float*)d_in[4];
    const float* W_c    = (const float*)d_in[5];
    const float* b_c    = (const float*)d_in[6];
    const float* w_a    = (const float*)d_in[7];
    const float* W_ih   = (const float*)d_in[8];
    const float* W_hh   = (const float*)d_in[9];
    const float* b_ih   = (const float*)d_in[10];
    const float* b_hh   = (const float*)d_in[11];
    const float* W_p    = (const float*)d_in[12];
    const float* b_p    = (const float*)d_in[13];
    float* out = (float*)d_out;

    float* WhT; cudaGetSymbolAddress((void**)&WhT, g_WhT);
    float* WcT; cudaGetSymbolAddress((void**)&WcT, g_WcT);
    float* WpT; cudaGetSymbolAddress((void**)&WpT, g_WpT);
    float* WgT; cudaGetSymbolAddress((void**)&WgT, g_WgT);
    float* bg;  cudaGetSymbolAddress((void**)&bg,  g_bg);
    float* annproj; cudaGetSymbolAddress((void**)&annproj, g_annproj);
    float* hbuf; cudaGetSymbolAddress((void**)&hbuf, g_h);
    float* hproj; cudaGetSymbolAddress((void**)&hproj, g_hproj);
    float* attn; cudaGetSymbolAddress((void**)&attn, g_attn);
    float* Xall; cudaGetSymbolAddress((void**)&Xall, g_X);
    float* gates; cudaGetSymbolAddress((void**)&gates, g_gates);

    dim3 tb(32, 8);
    // transposes
    transpose_kernel<<<dim3(ceil_div(ECH, 32), ceil_div(H, 32)), tb>>>(W_h, WhT, H, ECH);
    transpose_kernel<<<dim3(ceil_div(H + A2, 32), ceil_div(H, 32)), tb>>>(W_c, WcT, H, H + A2);
    transpose_kernel<<<dim3(ceil_div(KX, 32), ceil_div(V, 32)), tb>>>(W_p, WpT, V, KX);
    {
        size_t total = (size_t)KX * 4000;
        build_wg_kernel<<<(int)((total + 255) / 256), 256>>>(W_ih, W_hh, WgT);
        build_bg_kernel<<<ceil_div(4000, 256), 256>>>(b_ih, b_hh, bg);
    }
    // zero preds[0], attns[0]
    {
        size_t total = (size_t)B * V + S * B;
        zero_kernel<<<(int)((total + 255) / 256), 256>>>(out);
    }
    // h0 = tanh(ann[0,:,ECH:] @ W_h^T + b_h)  -> g_h[0]
    gemm_kernel<<<dim3(ceil_div(H, 64), ceil_div(B, 32)), 128>>>(
        WhT, ann + ECH, b_h, hbuf, 1LL, (long long)H, H, B, ECH, H, A2, 1);
    // annproj = ann @ W_c[:,1000:]^T + b_c  -> [s*B+b][j]
    gemm_kernel<<<dim3(ceil_div(H, 64), ceil_div(S * B, 32)), 128>>>(
        WcT + (size_t)H * H, ann, b_c, annproj, 1LL, (long long)H, H, S * B, A2, H, A2, 0);

    int cur = 0;
    for (int t = 1; t <= NSTEP; t++) {
        int st = t - 1;
        float* h_cur = hbuf + (size_t)cur * B * H;
        float* h_nxt = hbuf + (size_t)(1 - cur) * B * H;
        float* Xs = Xall + (size_t)st * B * KX;

        // hproj = h @ W_c[:, :1000]^T
        gemm_kernel<<<dim3(ceil_div(H, 64), 1), 128>>>(
            WcT, h_cur, (const float*)nullptr, hproj, 1LL, (long long)H, H, B, H, H, H, 0);
        // scores + softmax over batch; also writes attns[t]
        scores_softmax_kernel<<<S, 256>>>(hproj, annproj, w_a, attn,
                                          out + ATT_OFF + (size_t)t * S * B);
        // build X slice (embed gather, h copy, context)
        build_x_kernel<<<ceil_div(B * KX, 256), 256>>>(
            tokens + (size_t)(t - 1) * B, emb, h_cur, attn, ann, Xs);
        // GRU gates GEMM -> gates[b][4000]
        gemm_kernel<<<dim3(ceil_div(4000, 64), 1), 128>>>(
            WgT, Xs, bg, gates, 1LL, 4000LL, 4000, B, KX, 4000, KX, 0);
        // combine -> h_nxt (and hidden output at final step)
        gru_combine_kernel<<<ceil_div(B * H, 256), 256>>>(
            gates, h_cur, h_nxt, (t == NSTEP) ? (out + HID_OFF) : (float*)nullptr);
        cur = 1 - cur;
    }

    // batched prediction logits for all steps -> preds[1..49], then log-softmax in place
    gemm_kernel<<<dim3(ceil_div(V, 64), ceil_div(NPRED, 32)), 128>>>(
        WpT, Xall, b_p, out + (size_t)B * V, 1LL, (long long)V, V, NPRED, KX, V, KX, 0);
    logsoftmax_kernel<<<NPRED, 256>>>(out + (size_t)B * V);
}

// round 10
// speedup vs baseline: 2.7243x; 2.7243x over previous
#include <cuda_runtime.h>
#include <cuda_bf16.h>
#include <math.h>
#include <stdint.h>

// ---------------- problem constants ----------------
#define EMB   620
#define ECH   1000
#define A2    2000      // 2*ECH
#define H     1000      // DCH
#define V     30000
#define S     50
#define T     50
#define B     32
#define KX    3620      // EMB + H + A2
#define KP    3648      // KX padded to 32 (114 * 32)
#define NSTEP (T-1)     // 49
#define NPRED (NSTEP*B) // 1568

#define PRED_ELEMS  ((size_t)T*B*V)
#define HID_OFF     PRED_ELEMS
#define ATT_OFF     (PRED_ELEMS + (size_t)B*H)

// ---------------- device scratch (static, no allocation) ----------------
__device__ float g_WhT[ECH * H];
__device__ float g_WcT[(H + A2) * H];
__device__ float g_Wp_pack[(size_t)V * KP];   // tf32-rounded, K padded
__device__ float g_WgT[(size_t)KX * 4000];
__device__ float g_bg[4000];
__device__ float g_annproj[S * B * H];
__device__ float g_h[2][B * H];
__device__ float g_hpart[4 * B * H];
__device__ float g_attn[S * B];
__device__ float g_X[(size_t)NPRED * KP];     // fp32 (recurrence), K padded with zeros
__device__ float g_Xt[(size_t)NPRED * KP];    // tf32-rounded copy (pred GEMM)
__device__ float g_gpart[4 * B * 4000];

// ==================== helpers ====================
__device__ __forceinline__ void cp16(uint32_t dst, const void* src, bool valid) {
    int sz = valid ? 16 : 0;
    asm volatile("cp.async.cg.shared.global [%0], [%1], 16, %2;" :: "r"(dst), "l"(src), "r"(sz));
}
__device__ __forceinline__ uint32_t smem_u32(const void* p) {
    uint32_t a;
    asm("{ .reg .u64 t; cvta.to.shared.u64 t, %1; cvt.u32.u64 %0, t; }" : "=r"(a) : "l"(p));
    return a;
}
__device__ __forceinline__ float tf32_rna(float v) {
    uint32_t b;
    asm("cvt.rna.tf32.f32 %0, %1;" : "=r"(b) : "f"(v));
    return __uint_as_float(b);
}
__device__ __forceinline__ void mma_tf32(float* c, const uint32_t* a, const uint32_t* b) {
    asm volatile(
        "mma.sync.aligned.m16n8k8.row.col.f32.tf32.tf32.f32 "
        "{%0,%1,%2,%3}, {%4,%5,%6,%7}, {%8,%9}, {%0,%1,%2,%3};"
        : "+f"(c[0]), "+f"(c[1]), "+f"(c[2]), "+f"(c[3])
        : "r"(a[0]), "r"(a[1]), "r"(a[2]), "r"(a[3]), "r"(b[0]), "r"(b[1]));
}

// ==================== tf32 mma.sync prediction GEMM ====================
// out[n*V + m] = sum_k Wp[m][k] * Xt[n][k] + b_p[m]
// Tile: BM=128, BN=64, BK=32. 256 threads = 8 warps (4 m x 2 n), warp tile 32x32.
// SMEM: double-buffered As[128][36], Bs[64][36]; epilogue staged via Cs[64][132].
#define PM_AS_STRIDE 36
#define PM_BUF_F     6912              // floats per buffer: 128*36 + 64*36
#define PM_SMEM_B    (2 * PM_BUF_F * 4)  // 55296 bytes
#define PM_KSTAGES   (KP / 32)         // 114
#define PM_CS_STRIDE 132

__global__ void __launch_bounds__(256, 1)
pred_mma_kernel(const float* __restrict__ Wp, const float* __restrict__ Xt,
                const float* __restrict__ b_p, float* __restrict__ outp) {
    extern __shared__ float sm[];
    int tid = threadIdx.x;
    int lane = tid & 31, wid = tid >> 5;
    int wm = wid & 3, wn = wid >> 2;
    int n0 = blockIdx.x * 64;
    int m0 = blockIdx.y * 128;
    uint32_t sbase = smem_u32(sm);

    float c_[2][4][4];
    #pragma unroll
    for (int mi = 0; mi < 2; mi++)
        #pragma unroll
        for (int ni = 0; ni < 4; ni++)
            #pragma unroll
            for (int r = 0; r < 4; r++) c_[mi][ni][r] = 0.f;

    // stage loader: buf in {0,1}, sigma = k-stage index
    auto load_stage = [&](int buf, int sigma) {
        uint32_t abase = sbase + buf * PM_BUF_F * 4;
        uint32_t bbase = abase + 128 * PM_AS_STRIDE * 4;
        int k0 = sigma * 32;
        // A: 128 rows x 8 float4
        #pragma unroll
        for (int j = 0; j < 4; j++) {
            int idx = tid + j * 256;
            int row = idx >> 3, c4 = idx & 7;
            int m = m0 + row;
            bool valid = m < V;
            cp16(abase + row * (PM_AS_STRIDE * 4) + c4 * 16,
                 Wp + (size_t)(valid ? m : 0) * KP + k0 + c4 * 4, valid);
        }
        // B: 64 rows x 8 float4
        #pragma unroll
        for (int j = 0; j < 2; j++) {
            int idx = tid + j * 256;
            int row = idx >> 3, c4 = idx & 7;
            int n = n0 + row;
            bool valid = n < NPRED;
            cp16(bbase + row * (PM_AS_STRIDE * 4) + c4 * 16,
                 Xt + (size_t)(valid ? n : 0) * KP + k0 + c4 * 4, valid);
        }
    };

    load_stage(0, 0);
    asm volatile("cp.async.commit_group;" ::: "memory");

    int lr = lane >> 2, lc = lane & 3;
    #pragma unroll 1
    for (int s = 0; s < PM_KSTAGES; s++) {
        if (s + 1 < PM_KSTAGES) load_stage((s + 1) & 1, s + 1);
        asm volatile("cp.async.commit_group;" ::: "memory");
        asm volatile("cp.async.wait_group 1;" ::: "memory");
        __syncthreads();

        const float* As = sm + (s & 1) * PM_BUF_F;
        const float* Bs = As + 128 * PM_AS_STRIDE;
        #pragma unroll
        for (int k8 = 0; k8 < 4; k8++) {
            int k = k8 * 8;
            uint32_t a[2][4], b[4][2];
            #pragma unroll
            for (int mi = 0; mi < 2; mi++) {
                int r = wm * 32 + mi * 16 + lr;
                a[mi][0] = __float_as_uint(As[r * PM_AS_STRIDE + k + lc]);
                a[mi][1] = __float_as_uint(As[(r + 8) * PM_AS_STRIDE + k + lc]);
                a[mi][2] = __float_as_uint(As[r * PM_AS_STRIDE + k + lc + 4]);
                a[mi][3] = __float_as_uint(As[(r + 8) * PM_AS_STRIDE + k + lc + 4]);
            }
            #pragma unroll
            for (int ni = 0; ni < 4; ni++) {
                int n = wn * 32 + ni * 8 + lr;
                b[ni][0] = __float_as_uint(Bs[n * PM_AS_STRIDE + k + lc]);
                b[ni][1] = __float_as_uint(Bs[n * PM_AS_STRIDE + k + lc + 4]);
            }
            #pragma unroll
            for (int mi = 0; mi < 2; mi++)
                #pragma unroll
                for (int ni = 0; ni < 4; ni++)
                    mma_tf32(c_[mi][ni], a[mi], b[ni]);
        }
        __syncthreads();
    }

    // ---- epilogue: stage C^T tile in smem, then coalesced store ----
    // Cs[n_local][m_local], stride 132 floats
    float* Cs = sm;
    #pragma unroll
    for (int mi = 0; mi < 2; mi++) {
        int ml = wm * 32 + mi * 16 + lr;
        #pragma unroll
        for (int ni = 0; ni < 4; ni++) {
            int nl = wn * 32 + ni * 8 + lc * 2;
            Cs[nl * PM_CS_STRIDE + ml]            = c_[mi][ni][0];
            Cs[(nl + 1) * PM_CS_STRIDE + ml]      = c_[mi][ni][1];
            Cs[nl * PM_CS_STRIDE + ml + 8]        = c_[mi][ni][2];
            Cs[(nl + 1) * PM_CS_STRIDE + ml + 8]  = c_[mi][ni][3];
        }
    }
    __syncthreads();
    #pragma unroll
    for (int j = 0; j < 8; j++) {
        int idx = tid + j * 256;
        int row = idx >> 5, c4 = idx & 31;
        int n = n0 + row;
        int m = m0 + c4 * 4;
        if (n < NPRED && m + 3 < V) {
            float4 v = *reinterpret_cast<const float4*>(&Cs[row * PM_CS_STRIDE + c4 * 4]);
            float4 bb = *reinterpret_cast<const float4*>(&b_p[m]);
            v.x += bb.x; v.y += bb.y; v.z += bb.z; v.w += bb.w;
            *reinterpret_cast<float4*>(outp + (size_t)n * V + m) = v;
        }
    }
}

// ==================== packing / setup kernels ====================
__global__ void pack_wp_kernel(const float* __restrict__ W_p, float* __restrict__ Wp) {
    size_t i = (size_t)blockIdx.x * blockDim.x + threadIdx.x;
    size_t total = (size_t)V * (KP / 4);
    if (i >= total) return;
    int m = (int)(i / (KP / 4));
    int k = (int)(i % (KP / 4)) * 4;
    float4 o;
    o.x = (k + 0 < KX) ? tf32_rna(W_p[(size_t)m * KX + k + 0]) : 0.f;
    o.y = (k + 1 < KX) ? tf32_rna(W_p[(size_t)m * KX + k + 1]) : 0.f;
    o.z = (k + 2 < KX) ? tf32_rna(W_p[(size_t)m * KX + k + 2]) : 0.f;
    o.w = (k + 3 < KX) ? tf32_rna(W_p[(size_t)m * KX + k + 3]) : 0.f;
    *reinterpret_cast<float4*>(Wp + (size_t)m * KP + k) = o;
}

__global__ void transpose_kernel(const float* __restrict__ in, float* __restrict__ out,
                                 int R, int C) {
    __shared__ float tile[32][33];
    int c0 = blockIdx.x * 32, r0 = blockIdx.y * 32;
    int tx = threadIdx.x, ty = threadIdx.y;
    #pragma unroll
    for (int i = 0; i < 32; i += 8) {
        int r = r0 + ty + i, c = c0 + tx;
        tile[ty + i][tx] = (r < R && c < C) ? in[(size_t)r * C + c] : 0.f;
    }
    __syncthreads();
    #pragma unroll
    for (int i = 0; i < 32; i += 8) {
        int c = c0 + ty + i, r = r0 + tx;
        if (r < R && c < C) out[(size_t)c * R + r] = tile[tx][ty + i];
    }
}

__global__ void build_wg_kernel(const float* __restrict__ W_ih,
                                const float* __restrict__ W_hh,
                                float* __restrict__ WgT) {
    size_t idx = (size_t)blockIdx.x * blockDim.x + threadIdx.x;
    size_t total = (size_t)KX * 4000;
    if (idx >= total) return;
    int row = (int)(idx % 4000);
    int k   = (int)(idx / 4000);
    float v = 0.f;
    if (row < 2000) {
        if (k < EMB)              v = W_ih[(size_t)row * 2620 + k];
        else if (k < EMB + H)     v = W_hh[(size_t)row * H + (k - EMB)];
        else                      v = W_ih[(size_t)row * 2620 + (k - H)];
    } else if (row < 3000) {
        if (k < EMB)              v = W_ih[(size_t)row * 2620 + k];
        else if (k >= EMB + H)    v = W_ih[(size_t)row * 2620 + (k - H)];
    } else {
        if (k >= EMB && k < EMB + H) v = W_hh[(size_t)(row - 1000) * H + (k - EMB)];
    }
    WgT[(size_t)k * 4000 + row] = v;
}

__global__ void build_bg_kernel(const float* __restrict__ b_ih,
                                const float* __restrict__ b_hh,
                                float* __restrict__ bg) {
    int r = blockIdx.x * blockDim.x + threadIdx.x;
    if (r >= 4000) return;
    float v;
    if (r < 2000)      v = b_ih[r] + b_hh[r];
    else if (r < 3000) v = b_ih[r];
    else               v = b_hh[r - 1000];
    bg[r] = v;
}

// ==================== FFMA GEMMs (small/setup + split-K recurrence) ====================
__global__ void __launch_bounds__(128)
gemm_kernel(const float* __restrict__ AT, const float* __restrict__ Xp,
            const float* __restrict__ bias, float* __restrict__ C,
            long long cm, long long cn, int M, int N, int K,
            int ldA, int ldX, int act) {
    __shared__ float Ws[32][64];
    __shared__ float Xs[32][33];
    int bm = blockIdx.x * 64, bn = blockIdx.y * 32;
    int tid = threadIdx.x;
    int tm = tid >> 3, tn = tid & 7;
    float acc[4][4];
    #pragma unroll
    for (int i = 0; i < 4; i++)
        #pragma unroll
        for (int j = 0; j < 4; j++) acc[i][j] = 0.f;
    int a_m = tid & 63, a_k0 = tid >> 6, x_k = tid & 31, x_n0 = tid >> 5;
    for (int k0 = 0; k0 < K; k0 += 32) {
        #pragma unroll
        for (int p = 0; p < 16; p++) {
            int kk = p * 2 + a_k0, m = bm + a_m, kg = k0 + kk;
            Ws[kk][a_m] = (kg < K && m < M) ? AT[(size_t)kg * ldA + m] : 0.f;
        }
        #pragma unroll
        for (int p = 0; p < 8; p++) {
            int nn = p * 4 + x_n0, n = bn + nn, kg = k0 + x_k;
            Xs[x_k][nn] = (n < N && kg < K) ? Xp[(size_t)n * ldX + kg] : 0.f;
        }
        __syncthreads();
        #pragma unroll
        for (int kk = 0; kk < 32; kk++) {
            float4 wv = *reinterpret_cast<const float4*>(&Ws[kk][tm * 4]);
            float x0 = Xs[kk][tn * 4 + 0], x1 = Xs[kk][tn * 4 + 1];
            float x2 = Xs[kk][tn * 4 + 2], x3 = Xs[kk][tn * 4 + 3];
            acc[0][0] += wv.x * x0; acc[0][1] += wv.x * x1; acc[0][2] += wv.x * x2; acc[0][3] += wv.x * x3;
            acc[1][0] += wv.y * x0; acc[1][1] += wv.y * x1; acc[1][2] += wv.y * x2; acc[1][3] += wv.y * x3;
            acc[2][0] += wv.z * x0; acc[2][1] += wv.z * x1; acc[2][2] += wv.z * x2; acc[2][3] += wv.z * x3;
            acc[3][0] += wv.w * x0; acc[3][1] += wv.w * x1; acc[3][2] += wv.w * x2; acc[3][3] += wv.w * x3;
        }
        __syncthreads();
    }
    #pragma unroll
    for (int i = 0; i < 4; i++) {
        int m = bm + tm * 4 + i;
        if (m >= M) continue;
        float bb = bias ? bias[m] : 0.f;
        #pragma unroll
        for (int j = 0; j < 4; j++) {
            int n = bn + tn * 4 + j;
            if (n >= N) continue;
            float v = acc[i][j] + bb;
            if (act == 1) v = tanhf(v);
            C[(long long)m * cm + (long long)n * cn] = v;
        }
    }
}

__global__ void __launch_bounds__(128)
gemm_splitk_kernel(const float* __restrict__ AT, const float* __restrict__ Xp,
                   float* __restrict__ Cpart, int M, int N, int K,
                   int ldA, int ldX, int ks) {
    __shared__ float Ws[32][64];
    __shared__ float Xs[32][33];
    int bm = blockIdx.x * 64, bn = blockIdx.y * 32;
    int kb = blockIdx.z * ks;
    int ke = min(K, kb + ks);
    int tid = threadIdx.x;
    int tm = tid >> 3, tn = tid & 7;
    float acc[4][4];
    #pragma unroll
    for (int i = 0; i < 4; i++)
        #pragma unroll
        for (int j = 0; j < 4; j++) acc[i][j] = 0.f;
    int a_m = tid & 63, a_k0 = tid >> 6, x_k = tid & 31, x_n0 = tid >> 5;
    for (int k0 = kb; k0 < ke; k0 += 32) {
        #pragma unroll
        for (int p = 0; p < 16; p++) {
            int kk = p * 2 + a_k0, m = bm + a_m, kg = k0 + kk;
            Ws[kk][a_m] = (kg < ke && m < M) ? AT[(size_t)kg * ldA + m] : 0.f;
        }
        #pragma unroll
        for (int p = 0; p < 8; p++) {
            int nn = p * 4 + x_n0, n = bn + nn, kg = k0 + x_k;
            Xs[x_k][nn] = (n < N && kg < ke) ? Xp[(size_t)n * ldX + kg] : 0.f;
        }
        __syncthreads();
        #pragma unroll
        for (int kk = 0; kk < 32; kk++) {
            float4 wv = *reinterpret_cast<const float4*>(&Ws[kk][tm * 4]);
            float x0 = Xs[kk][tn * 4 + 0], x1 = Xs[kk][tn * 4 + 1];
            float x2 = Xs[kk][tn * 4 + 2], x3 = Xs[kk][tn * 4 + 3];
            acc[0][0] += wv.x * x0; acc[0][1] += wv.x * x1; acc[0][2] += wv.x * x2; acc[0][3] += wv.x * x3;
            acc[1][0] += wv.y * x0; acc[1][1] += wv.y * x1; acc[1][2] += wv.y * x2; acc[1][3] += wv.y * x3;
            acc[2][0] += wv.z * x0; acc[2][1] += wv.z * x1; acc[2][2] += wv.z * x2; acc[2][3] += wv.z * x3;
            acc[3][0] += wv.w * x0; acc[3][1] += wv.w * x1; acc[3][2] += wv.w * x2; acc[3][3] += wv.w * x3;
        }
        __syncthreads();
    }
    float* Cz = Cpart + (size_t)blockIdx.z * M * N;
    #pragma unroll
    for (int i = 0; i < 4; i++) {
        int m = bm + tm * 4 + i;
        if (m >= M) continue;
        #pragma unroll
        for (int j = 0; j < 4; j++) {
            int n = bn + tn * 4 + j;
            if (n >= N) continue;
            Cz[(size_t)n * M + m] = acc[i][j];
        }
    }
}

// ==================== recurrence helper kernels ====================
__global__ void scores_softmax_kernel(const float* __restrict__ hpart,
                                      const float* __restrict__ annproj,
                                      const float* __restrict__ w_a,
                                      float* __restrict__ attn,
                                      float* __restrict__ attns_out) {
    int s = blockIdx.x;
    int warp = threadIdx.x >> 5;
    int lane = threadIdx.x & 31;
    __shared__ float sm_scores[B];
    for (int it = 0; it < 4; it++) {
        int b = warp + it * 8;
        const float* ap = annproj + (size_t)(s * B + b) * H;
        float sum = 0.f;
        for (int j = lane; j < H; j += 32) {
            float hp = hpart[b * H + j] + hpart[B * H + b * H + j]
                     + hpart[2 * B * H + b * H + j] + hpart[3 * B * H + b * H + j];
            sum += tanhf(hp + ap[j]) * w_a[j];
        }
        #pragma unroll
        for (int o = 16; o > 0; o >>= 1) sum += __shfl_down_sync(0xffffffffu, sum, o);
        if (lane == 0) sm_scores[b] = sum;
    }
    __syncthreads();
    if (warp == 0) {
        float x = sm_scores[lane];
        float mx = x;
        #pragma unroll
        for (int o = 16; o > 0; o >>= 1) mx = fmaxf(mx, __shfl_xor_sync(0xffffffffu, mx, o));
        float e = expf(x - mx);
        float sum = e;
        #pragma unroll
        for (int o = 16; o > 0; o >>= 1) sum += __shfl_xor_sync(0xffffffffu, sum, o);
        float a = e / sum;
        attn[s * B + lane] = a;
        attns_out[s * B + lane] = a;
    }
}

__global__ void build_x_kernel(const int* __restrict__ tokens_t,
                               const float* __restrict__ emb,
                               const float* __restrict__ h_prev,
                               const float* __restrict__ attn,
                               const float* __restrict__ ann,
                               float* __restrict__ Xslice,
                               float* __restrict__ Xtslice) {
    int idx = blockIdx.x * blockDim.x + threadIdx.x;
    if (idx >= B * KP) return;
    int b = idx / KP;
    int e = idx % KP;
    float v = 0.f;
    if (e < EMB) {
        int tok = tokens_t[b];
        v = emb[(size_t)tok * EMB + e];
    } else if (e < EMB + H) {
        v = h_prev[b * H + (e - EMB)];
    } else if (e < KX) {
        int c = e - (EMB + H);
        float sum = 0.f;
        #pragma unroll 5
        for (int s = 0; s < S; s++)
            sum += attn[s * B + b] * ann[(size_t)(s * B + b) * A2 + c];
        v = sum;
    }
    Xslice[(size_t)b * KP + e] = v;
    Xtslice[(size_t)b * KP + e] = tf32_rna(v);
}

__global__ void gru_combine_kernel(const float* __restrict__ gpart,
                                   const float* __restrict__ bg,
                                   const float* __restrict__ h_old,
                                   float* __restrict__ h_new,
                                   float* __restrict__ hid_out) {
    int idx = blockIdx.x * blockDim.x + threadIdx.x;
    if (idx >= B * H) return;
    int b = idx / H, j = idx % H;
    const size_t pb = (size_t)B * 4000;
    #define GSUM(off) (gpart[(size_t)b*4000 + (off) + j] + gpart[pb + (size_t)b*4000 + (off) + j] \
                     + gpart[2*pb + (size_t)b*4000 + (off) + j] + gpart[3*pb + (size_t)b*4000 + (off) + j])
    float gr = GSUM(0)    + bg[j];
    float gz = GSUM(1000) + bg[1000 + j];
    float gi = GSUM(2000) + bg[2000 + j];
    float gh = GSUM(3000) + bg[3000 + j];
    #undef GSUM
    float r  = 1.f / (1.f + expf(-gr));
    float z  = 1.f / (1.f + expf(-gz));
    float nn = tanhf(gi + r * gh);
    float hv = (1.f - z) * nn + z * h_old[idx];
    h_new[idx] = hv;
    if (hid_out) hid_out[idx] = hv;
}

__global__ void zero_kernel(float* __restrict__ out) {
    size_t idx = (size_t)blockIdx.x * blockDim.x + threadIdx.x;
    size_t n0 = (size_t)B * V;
    if (idx < n0) out[idx] = 0.f;
    else if (idx < n0 + S * B) out[ATT_OFF + (idx - n0)] = 0.f;
}

__global__ void logsoftmax_kernel(float* __restrict__ preds_base) {
    int row = blockIdx.x;
    float* p = preds_base + (size_t)row * V;
    int tid = threadIdx.x;
    __shared__ float red[8];
    float mx = -1e30f;
    for (int i = tid; i < V; i += 256) mx = fmaxf(mx, p[i]);
    #pragma unroll
    for (int o = 16; o > 0; o >>= 1) mx = fmaxf(mx, __shfl_xor_sync(0xffffffffu, mx, o));
    if ((tid & 31) == 0) red[tid >> 5] = mx;
    __syncthreads();
    if (tid < 8) {
        float v = red[tid];
        #pragma unroll
        for (int o = 4; o > 0; o >>= 1) v = fmaxf(v, __shfl_xor_sync(0xffu, v, o));
        red[tid] = v;
    }
    __syncthreads();
    mx = red[0];
    __syncthreads();
    float sum = 0.f;
    for (int i = tid; i < V; i += 256) sum += expf(p[i] - mx);
    #pragma unroll
    for (int o = 16; o > 0; o >>= 1) sum += __shfl_xor_sync(0xffffffffu, sum, o);
    if ((tid & 31) == 0) red[tid >> 5] = sum;
    __syncthreads();
    if (tid < 8) {
        float v = red[tid];
        #pragma unroll
        for (int o = 4; o > 0; o >>= 1) v += __shfl_xor_sync(0xffu, v, o);
        red[tid] = v;
    }
    __syncthreads();
    float lse = mx + logf(red[0]);
    for (int i = tid; i < V; i += 256) p[i] = p[i] - lse;
}

// ==================== host orchestration ====================
static inline int ceil_div(int a, int b) { return (a + b - 1) / b; }

extern "C" void kernel_launch(void* const* d_in, const int* in_sizes, int n_in,
                              void* d_out, int out_size) {
    const int*   tokens = (const int*)  d_in[0];
    const float* ann    = (const float*)d_in[1];
    const float* emb    = (const float*)d_in[2];
    const float* W_h    = (const float*)d_in[3];
    const float* b_h    = (const float*)d_in[4];
    const float* W_c    = (const float*)d_in[5];
    const float* b_c    = (const float*)d_in[6];
    const float* w_a    = (const float*)d_in[7];
    const float* W_ih   = (const float*)d_in[8];
    const float* W_hh   = (const float*)d_in[9];
    const float* b_ih   = (const float*)d_in[10];
    const float* b_hh   = (const float*)d_in[11];
    const float* W_p    = (const float*)d_in[12];
    const float* b_p    = (const float*)d_in[13];
    float* out = (float*)d_out;

    float* WhT;  cudaGetSymbolAddress((void**)&WhT, g_WhT);
    float* WcT;  cudaGetSymbolAddress((void**)&WcT, g_WcT);
    float* WpP;  cudaGetSymbolAddress((void**)&WpP, g_Wp_pack);
    float* WgT;  cudaGetSymbolAddress((void**)&WgT, g_WgT);
    float* bg;   cudaGetSymbolAddress((void**)&bg,  g_bg);
    float* annproj; cudaGetSymbolAddress((void**)&annproj, g_annproj);
    float* hbuf; cudaGetSymbolAddress((void**)&hbuf, g_h);
    float* hpart; cudaGetSymbolAddress((void**)&hpart, g_hpart);
    float* attn; cudaGetSymbolAddress((void**)&attn, g_attn);
    float* Xall; cudaGetSymbolAddress((void**)&Xall, g_X);
    float* Xtall; cudaGetSymbolAddress((void**)&Xtall, g_Xt);
    float* gpart; cudaGetSymbolAddress((void**)&gpart, g_gpart);

    cudaFuncSetAttribute(pred_mma_kernel,
                         cudaFuncAttributeMaxDynamicSharedMemorySize, PM_SMEM_B);

    dim3 tb(32, 8);
    transpose_kernel<<<dim3(ceil_div(ECH, 32), ceil_div(H, 32)), tb>>>(W_h, WhT, H, ECH);
    transpose_kernel<<<dim3(ceil_div(H + A2, 32), ceil_div(H, 32)), tb>>>(W_c, WcT, H, H + A2);
    {
        size_t total = (size_t)V * (KP / 4);
        pack_wp_kernel<<<(int)((total + 255) / 256), 256>>>(W_p, WpP);
        size_t t2 = (size_t)KX * 4000;
        build_wg_kernel<<<(int)((t2 + 255) / 256), 256>>>(W_ih, W_hh, WgT);
        build_bg_kernel<<<ceil_div(4000, 256), 256>>>(b_ih, b_hh, bg);
        size_t t3 = (size_t)B * V + S * B;
        zero_kernel<<<(int)((t3 + 255) / 256), 256>>>(out);
    }
    // h0 = tanh(ann[0,:,ECH:] @ W_h^T + b_h)
    gemm_kernel<<<dim3(ceil_div(H, 64), 1), 128>>>(
        WhT, ann + ECH, b_h, hbuf, 1LL, (long long)H, H, B, ECH, H, A2, 1);
    // annproj = ann @ W_c[:,1000:]^T + b_c
    gemm_kernel<<<dim3(ceil_div(H, 64), ceil_div(S * B, 32)), 128>>>(
        WcT + (size_t)H * H, ann, b_c, annproj, 1LL, (long long)H, H, S * B, A2, H, A2, 0);

    int cur = 0;
    for (int t = 1; t <= NSTEP; t++) {
        int st = t - 1;
        float* h_cur = hbuf + (size_t)cur * B * H;
        float* h_nxt = hbuf + (size_t)(1 - cur) * B * H;
        float* Xs  = Xall  + (size_t)st * B * KP;
        float* Xts = Xtall + (size_t)st * B * KP;

        gemm_splitk_kernel<<<dim3(ceil_div(H, 64), 1, 4), 128>>>(
            WcT, h_cur, hpart, H, B, H, H, H, 250);
        scores_softmax_kernel<<<S, 256>>>(hpart, annproj, w_a, attn,
                                          out + ATT_OFF + (size_t)t * S * B);
        build_x_kernel<<<ceil_div(B * KP, 256), 256>>>(
            tokens + (size_t)(t - 1) * B, emb, h_cur, attn, ann, Xs, Xts);
        gemm_splitk_kernel<<<dim3(ceil_div(4000, 64), 1, 4), 128>>>(
            WgT, Xs, gpart, 4000, B, KX, 4000, KP, 905);
        gru_combine_kernel<<<ceil_div(B * H, 256), 256>>>(
            gpart, bg, h_cur, h_nxt, (t == NSTEP) ? (out + HID_OFF) : (float*)nullptr);
        cur = 1 - cur;
    }

    // batched prediction logits (tf32 tensor cores) -> preds[1..49]
    pred_mma_kernel<<<dim3(ceil_div(NPRED, 64), ceil_div(V, 128)), 256, PM_SMEM_B>>>(
        WpP, Xtall, b_p, out + (size_t)B * V);
    logsoftmax_kernel<<<NPRED, 256>>>(out + (size_t)B * V);
}

// round 11
// speedup vs baseline: 3.3190x; 1.2183x over previous
#include <cuda_runtime.h>
#include <cuda_fp16.h>
#include <math.h>
#include <stdint.h>

// ---------------- problem constants ----------------
#define EMB   620
#define ECH   1000
#define A2    2000      // 2*ECH
#define H     1000      // DCH
#define V     30000
#define S     50
#define T     50
#define B     32
#define KX    3620      // EMB + H + A2
#define KP    3648      // KX padded (228 * 16)
#define NQ    228       // k16 chunks
#define NSTEP (T-1)     // 49
#define NPRED (NSTEP*B) // 1568
#define MT_TILES 235    // ceil(V/128)
#define NT_TILES 25     // ceil(NPRED/64)

#define PRED_ELEMS  ((size_t)T*B*V)
#define HID_OFF     PRED_ELEMS
#define ATT_OFF     (PRED_ELEMS + (size_t)B*H)

// ---------------- device scratch (static, no allocation) ----------------
__device__ float g_WhT[ECH * H];
__device__ float g_WcT[(H + A2) * H];
__device__ uint32_t g_Wph[(size_t)MT_TILES * NQ * 1024];  // fragment-major fp16 Wp
__device__ uint32_t g_Xh[(size_t)NT_TILES * NQ * 512];    // fragment-major fp16 X
__device__ float g_WgT[(size_t)KX * 4000];
__device__ float g_bg[4000];
__device__ float g_annproj[S * B * H];
__device__ float g_h[2][B * H];
__device__ float g_hpart[4 * B * H];
__device__ float g_attn[S * B];
__device__ float g_X[(size_t)NPRED * KP];     // fp32 (recurrence), K padded with zeros
__device__ float g_gpart[4 * B * 4000];

// ==================== helpers ====================
__device__ __forceinline__ void cp16(uint32_t dst, const void* src) {
    asm volatile("cp.async.cg.shared.global [%0], [%1], 16;" :: "r"(dst), "l"(src));
}
__device__ __forceinline__ uint32_t smem_u32(const void* p) {
    uint32_t a;
    asm("{ .reg .u64 t; cvta.to.shared.u64 t, %1; cvt.u32.u64 %0, t; }" : "=r"(a) : "l"(p));
    return a;
}
__device__ __forceinline__ void mma_f16(float* c, const uint32_t* a, const uint32_t* b) {
    asm volatile(
        "mma.sync.aligned.m16n8k16.row.col.f32.f16.f16.f32 "
        "{%0,%1,%2,%3}, {%4,%5,%6,%7}, {%8,%9}, {%0,%1,%2,%3};"
        : "+f"(c[0]), "+f"(c[1]), "+f"(c[2]), "+f"(c[3])
        : "r"(a[0]), "r"(a[1]), "r"(a[2]), "r"(a[3]), "r"(b[0]), "r"(b[1]));
}

// ==================== fragment packing kernels ====================
// A fragment layout (m16n8k16): reg r, lane l, halves h:
//   m = f*16 + (l>>2) + (r&1)*8 ; k(in q) = (l&3)*2 + (r>>1)*8 + h
// g_Wph index: (((mt*NQ + q)*8 + f)*32 + l)*4 + r   (u32 = 2 halves)
__global__ void pack_wp_h_kernel(const float* __restrict__ W_p, uint32_t* __restrict__ Wph) {
    size_t idx = (size_t)blockIdx.x * blockDim.x + threadIdx.x;
    size_t total = (size_t)MT_TILES * NQ * 1024;
    if (idx >= total) return;
    int r = (int)(idx & 3);
    int l = (int)((idx >> 2) & 31);
    int f = (int)((idx >> 7) & 7);
    size_t qmt = idx >> 10;
    int q  = (int)(qmt % NQ);
    int mt = (int)(qmt / NQ);
    int m = mt * 128 + f * 16 + (l >> 2) + (r & 1) * 8;
    int k = q * 16 + (l & 3) * 2 + (r >> 1) * 8;
    float v0 = (m < V && k     < KX) ? W_p[(size_t)m * KX + k]     : 0.f;
    float v1 = (m < V && k + 1 < KX) ? W_p[(size_t)m * KX + k + 1] : 0.f;
    __half2 hv = __floats2half2_rn(v0, v1);
    Wph[idx] = *reinterpret_cast<uint32_t*>(&hv);
}

// B fragment layout: reg r (0..1), lane l:
//   n = g*8 + (l>>2) ; k(in q) = (l&3)*2 + r*8 + h
// g_Xh index: (((nt*NQ + q)*8 + g)*32 + l)*2 + r
__global__ void pack_x_h_kernel(const float* __restrict__ X, uint32_t* __restrict__ Xh) {
    size_t idx = (size_t)blockIdx.x * blockDim.x + threadIdx.x;
    size_t total = (size_t)NT_TILES * NQ * 512;
    if (idx >= total) return;
    int r = (int)(idx & 1);
    int l = (int)((idx >> 1) & 31);
    int g = (int)((idx >> 6) & 7);
    size_t qnt = idx >> 9;
    int q  = (int)(qnt % NQ);
    int nt = (int)(qnt / NQ);
    int n = nt * 64 + g * 8 + (l >> 2);
    int k = q * 16 + (l & 3) * 2 + r * 8;
    float v0 = 0.f, v1 = 0.f;
    if (n < NPRED) {
        v0 = X[(size_t)n * KP + k];
        v1 = X[(size_t)n * KP + k + 1];
    }
    __half2 hv = __floats2half2_rn(v0, v1);
    Xh[idx] = *reinterpret_cast<uint32_t*>(&hv);
}

// ==================== fp16 mma.sync prediction GEMM ====================
// out[n*V + m] = sum_k Wp[m][k] * X[n][k] + b_p[m]
// Tile BM=128, BN=64, BK=32 (2 k16). 256 thr = 8 warps (4m x 2n), warp tile 32x32.
// Stage = A 8192B + B 4096B = 12288B; 4 stages = 49152B smem.
#define PM_NSTG   4
#define PM_STG_B  12288
#define PM_SMEM_B (PM_NSTG * PM_STG_B)
#define PM_KSTAGES (NQ / 2)   // 114
#define PM_CS_STRIDE 132

__global__ void __launch_bounds__(256, 1)
pred_mma_kernel(const uint32_t* __restrict__ Wph, const uint32_t* __restrict__ Xh,
                const float* __restrict__ b_p, float* __restrict__ outp) {
    extern __shared__ __align__(16) char smc[];
    uint32_t sbase = smem_u32(smc);
    int tid = threadIdx.x;
    int lane = tid & 31, wid = tid >> 5;
    int wm = wid & 3, wn = wid >> 2;
    int nt = blockIdx.x, mt = blockIdx.y;
    int n0 = nt * 64, m0 = mt * 128;

    const char* baseA = (const char*)Wph + (size_t)mt * NQ * 4096; // 4096B per q
    const char* baseB = (const char*)Xh + (size_t)nt * NQ * 2048;  // 2048B per q

    float c_[2][4][4];
    #pragma unroll
    for (int mi = 0; mi < 2; mi++)
        #pragma unroll
        for (int ni = 0; ni < 4; ni++)
            #pragma unroll
            for (int r = 0; r < 4; r++) c_[mi][ni][r] = 0.f;

    auto load_stage = [&](int buf, int s) {
        uint32_t da = sbase + buf * PM_STG_B;
        const char* sa = baseA + (size_t)s * 8192;
        cp16(da + tid * 16, sa + tid * 16);
        cp16(da + 4096 + tid * 16, sa + 4096 + tid * 16);
        const char* sb = baseB + (size_t)s * 4096;
        cp16(da + 8192 + tid * 16, sb + tid * 16);
    };

    #pragma unroll
    for (int j = 0; j < 3; j++) {
        load_stage(j, j);
        asm volatile("cp.async.commit_group;" ::: "memory");
    }

    #pragma unroll 1
    for (int s = 0; s < PM_KSTAGES; s++) {
        asm volatile("cp.async.wait_group 2;" ::: "memory");
        __syncthreads();
        int buf = s & 3;
        uint32_t su = sbase + buf * PM_STG_B;
        #pragma unroll
        for (int q2 = 0; q2 < 2; q2++) {
            uint32_t a[2][4], b[4][2];
            #pragma unroll
            for (int mi = 0; mi < 2; mi++) {
                uint32_t addr = su + q2 * 4096 + (wm * 2 + mi) * 512 + lane * 16;
                asm volatile("ld.shared.v4.b32 {%0,%1,%2,%3}, [%4];"
                             : "=r"(a[mi][0]), "=r"(a[mi][1]), "=r"(a[mi][2]), "=r"(a[mi][3])
                             : "r"(addr));
            }
            #pragma unroll
            for (int ni = 0; ni < 4; ni++) {
                uint32_t addr = su + 8192 + q2 * 2048 + (wn * 4 + ni) * 256 + lane * 8;
                asm volatile("ld.shared.v2.b32 {%0,%1}, [%2];"
                             : "=r"(b[ni][0]), "=r"(b[ni][1]) : "r"(addr));
            }
            #pragma unroll
            for (int mi = 0; mi < 2; mi++)
                #pragma unroll
                for (int ni = 0; ni < 4; ni++)
                    mma_f16(c_[mi][ni], a[mi], b[ni]);
        }
        int nx = s + 3;
        if (nx < PM_KSTAGES) load_stage(nx & 3, nx);
        asm volatile("cp.async.commit_group;" ::: "memory");
    }
    __syncthreads();

    // ---- epilogue: stage tile as Cs[n_local][m_local], then coalesced store ----
    float* Cs = (float*)smc;
    #pragma unroll
    for (int mi = 0; mi < 2; mi++) {
        int mlA = wm * 32 + mi * 16 + (lane >> 2);
        #pragma unroll
        for (int ni = 0; ni < 4; ni++) {
            int nl = wn * 32 + ni * 8 + (lane & 3) * 2;
            Cs[nl * PM_CS_STRIDE + mlA]           = c_[mi][ni][0];
            Cs[(nl + 1) * PM_CS_STRIDE + mlA]     = c_[mi][ni][1];
            Cs[nl * PM_CS_STRIDE + mlA + 8]       = c_[mi][ni][2];
            Cs[(nl + 1) * PM_CS_STRIDE + mlA + 8] = c_[mi][ni][3];
        }
    }
    __syncthreads();
    #pragma unroll
    for (int j = 0; j < 8; j++) {
        int idx = tid + j * 256;
        int row = idx >> 5, c4 = idx & 31;
        int n = n0 + row;
        int m = m0 + c4 * 4;
        if (n < NPRED && m + 3 < V) {
            float4 v = *reinterpret_cast<const float4*>(&Cs[row * PM_CS_STRIDE + c4 * 4]);
            float4 bb = *reinterpret_cast<const float4*>(&b_p[m]);
            v.x += bb.x; v.y += bb.y; v.z += bb.z; v.w += bb.w;
            *reinterpret_cast<float4*>(outp + (size_t)n * V + m) = v;
        }
    }
}

// ==================== setup kernels ====================
__global__ void transpose_kernel(const float* __restrict__ in, float* __restrict__ out,
                                 int R, int C) {
    __shared__ float tile[32][33];
    int c0 = blockIdx.x * 32, r0 = blockIdx.y * 32;
    int tx = threadIdx.x, ty = threadIdx.y;
    #pragma unroll
    for (int i = 0; i < 32; i += 8) {
        int r = r0 + ty + i, c = c0 + tx;
        tile[ty + i][tx] = (r < R && c < C) ? in[(size_t)r * C + c] : 0.f;
    }
    __syncthreads();
    #pragma unroll
    for (int i = 0; i < 32; i += 8) {
        int c = c0 + ty + i, r = r0 + tx;
        if (r < R && c < C) out[(size_t)c * R + r] = tile[tx][ty + i];
    }
}

__global__ void build_wg_kernel(const float* __restrict__ W_ih,
                                const float* __restrict__ W_hh,
                                float* __restrict__ WgT) {
    size_t idx = (size_t)blockIdx.x * blockDim.x + threadIdx.x;
    size_t total = (size_t)KX * 4000;
    if (idx >= total) return;
    int row = (int)(idx % 4000);
    int k   = (int)(idx / 4000);
    float v = 0.f;
    if (row < 2000) {
        if (k < EMB)              v = W_ih[(size_t)row * 2620 + k];
        else if (k < EMB + H)     v = W_hh[(size_t)row * H + (k - EMB)];
        else                      v = W_ih[(size_t)row * 2620 + (k - H)];
    } else if (row < 3000) {
        if (k < EMB)              v = W_ih[(size_t)row * 2620 + k];
        else if (k >= EMB + H)    v = W_ih[(size_t)row * 2620 + (k - H)];
    } else {
        if (k >= EMB && k < EMB + H) v = W_hh[(size_t)(row - 1000) * H + (k - EMB)];
    }
    WgT[(size_t)k * 4000 + row] = v;
}

__global__ void build_bg_kernel(const float* __restrict__ b_ih,
                                const float* __restrict__ b_hh,
                                float* __restrict__ bg) {
    int r = blockIdx.x * blockDim.x + threadIdx.x;
    if (r >= 4000) return;
    float v;
    if (r < 2000)      v = b_ih[r] + b_hh[r];
    else if (r < 3000) v = b_ih[r];
    else               v = b_hh[r - 1000];
    bg[r] = v;
}

// ==================== FFMA GEMMs (setup + split-K recurrence) ====================
__global__ void __launch_bounds__(128)
gemm_kernel(const float* __restrict__ AT, const float* __restrict__ Xp,
            const float* __restrict__ bias, float* __restrict__ C,
            long long cm, long long cn, int M, int N, int K,
            int ldA, int ldX, int act) {
    __shared__ float Ws[32][64];
    __shared__ float Xs[32][33];
    int bm = blockIdx.x * 64, bn = blockIdx.y * 32;
    int tid = threadIdx.x;
    int tm = tid >> 3, tn = tid & 7;
    float acc[4][4];
    #pragma unroll
    for (int i = 0; i < 4; i++)
        #pragma unroll
        for (int j = 0; j < 4; j++) acc[i][j] = 0.f;
    int a_m = tid & 63, a_k0 = tid >> 6, x_k = tid & 31, x_n0 = tid >> 5;
    for (int k0 = 0; k0 < K; k0 += 32) {
        #pragma unroll
        for (int p = 0; p < 16; p++) {
            int kk = p * 2 + a_k0, m = bm + a_m, kg = k0 + kk;
            Ws[kk][a_m] = (kg < K && m < M) ? AT[(size_t)kg * ldA + m] : 0.f;
        }
        #pragma unroll
        for (int p = 0; p < 8; p++) {
            int nn = p * 4 + x_n0, n = bn + nn, kg = k0 + x_k;
            Xs[x_k][nn] = (n < N && kg < K) ? Xp[(size_t)n * ldX + kg] : 0.f;
        }
        __syncthreads();
        #pragma unroll
        for (int kk = 0; kk < 32; kk++) {
            float4 wv = *reinterpret_cast<const float4*>(&Ws[kk][tm * 4]);
            float x0 = Xs[kk][tn * 4 + 0], x1 = Xs[kk][tn * 4 + 1];
            float x2 = Xs[kk][tn * 4 + 2], x3 = Xs[kk][tn * 4 + 3];
            acc[0][0] += wv.x * x0; acc[0][1] += wv.x * x1; acc[0][2] += wv.x * x2; acc[0][3] += wv.x * x3;
            acc[1][0] += wv.y * x0; acc[1][1] += wv.y * x1; acc[1][2] += wv.y * x2; acc[1][3] += wv.y * x3;
            acc[2][0] += wv.z * x0; acc[2][1] += wv.z * x1; acc[2][2] += wv.z * x2; acc[2][3] += wv.z * x3;
            acc[3][0] += wv.w * x0; acc[3][1] += wv.w * x1; acc[3][2] += wv.w * x2; acc[3][3] += wv.w * x3;
        }
        __syncthreads();
    }
    #pragma unroll
    for (int i = 0; i < 4; i++) {
        int m = bm + tm * 4 + i;
        if (m >= M) continue;
        float bb = bias ? bias[m] : 0.f;
        #pragma unroll
        for (int j = 0; j < 4; j++) {
            int n = bn + tn * 4 + j;
            if (n >= N) continue;
            float v = acc[i][j] + bb;
            if (act == 1) v = tanhf(v);
            C[(long long)m * cm + (long long)n * cn] = v;
        }
    }
}

__global__ void __launch_bounds__(128)
gemm_splitk_kernel(const float* __restrict__ AT, const float* __restrict__ Xp,
                   float* __restrict__ Cpart, int M, int N, int K,
                   int ldA, int ldX, int ks) {
    __shared__ float Ws[32][64];
    __shared__ float Xs[32][33];
    int bm = blockIdx.x * 64, bn = blockIdx.y * 32;
    int kb = blockIdx.z * ks;
    int ke = min(K, kb + ks);
    int tid = threadIdx.x;
    int tm = tid >> 3, tn = tid & 7;
    float acc[4][4];
    #pragma unroll
    for (int i = 0; i < 4; i++)
        #pragma unroll
        for (int j = 0; j < 4; j++) acc[i][j] = 0.f;
    int a_m = tid & 63, a_k0 = tid >> 6, x_k = tid & 31, x_n0 = tid >> 5;
    for (int k0 = kb; k0 < ke; k0 += 32) {
        #pragma unroll
        for (int p = 0; p < 16; p++) {
            int kk = p * 2 + a_k0, m = bm + a_m, kg = k0 + kk;
            Ws[kk][a_m] = (kg < ke && m < M) ? AT[(size_t)kg * ldA + m] : 0.f;
        }
        #pragma unroll
        for (int p = 0; p < 8; p++) {
            int nn = p * 4 + x_n0, n = bn + nn, kg = k0 + x_k;
            Xs[x_k][nn] = (n < N && kg < ke) ? Xp[(size_t)n * ldX + kg] : 0.f;
        }
        __syncthreads();
        #pragma unroll
        for (int kk = 0; kk < 32; kk++) {
            float4 wv = *reinterpret_cast<const float4*>(&Ws[kk][tm * 4]);
            float x0 = Xs[kk][tn * 4 + 0], x1 = Xs[kk][tn * 4 + 1];
            float x2 = Xs[kk][tn * 4 + 2], x3 = Xs[kk][tn * 4 + 3];
            acc[0][0] += wv.x * x0; acc[0][1] += wv.x * x1; acc[0][2] += wv.x * x2; acc[0][3] += wv.x * x3;
            acc[1][0] += wv.y * x0; acc[1][1] += wv.y * x1; acc[1][2] += wv.y * x2; acc[1][3] += wv.y * x3;
            acc[2][0] += wv.z * x0; acc[2][1] += wv.z * x1; acc[2][2] += wv.z * x2; acc[2][3] += wv.z * x3;
            acc[3][0] += wv.w * x0; acc[3][1] += wv.w * x1; acc[3][2] += wv.w * x2; acc[3][3] += wv.w * x3;
        }
        __syncthreads();
    }
    float* Cz = Cpart + (size_t)blockIdx.z * M * N;
    #pragma unroll
    for (int i = 0; i < 4; i++) {
        int m = bm + tm * 4 + i;
        if (m >= M) continue;
        #pragma unroll
        for (int j = 0; j < 4; j++) {
            int n = bn + tn * 4 + j;
            if (n >= N) continue;
            Cz[(size_t)n * M + m] = acc[i][j];
        }
    }
}

// ==================== recurrence helper kernels ====================
__global__ void scores_softmax_kernel(const float* __restrict__ hpart,
                                      const float* __restrict__ annproj,
                                      const float* __restrict__ w_a,
                                      float* __restrict__ attn,
                                      float* __restrict__ attns_out) {
    int s = blockIdx.x;
    int warp = threadIdx.x >> 5;
    int lane = threadIdx.x & 31;
    __shared__ float sm_scores[B];
    for (int it = 0; it < 4; it++) {
        int b = warp + it * 8;
        const float* ap = annproj + (size_t)(s * B + b) * H;
        float sum = 0.f;
        for (int j = lane; j < H; j += 32) {
            float hp = hpart[b * H + j] + hpart[B * H + b * H + j]
                     + hpart[2 * B * H + b * H + j] + hpart[3 * B * H + b * H + j];
            sum += tanhf(hp + ap[j]) * w_a[j];
        }
        #pragma unroll
        for (int o = 16; o > 0; o >>= 1) sum += __shfl_down_sync(0xffffffffu, sum, o);
        if (lane == 0) sm_scores[b] = sum;
    }
    __syncthreads();
    if (warp == 0) {
        float x = sm_scores[lane];
        float mx = x;
        #pragma unroll
        for (int o = 16; o > 0; o >>= 1) mx = fmaxf(mx, __shfl_xor_sync(0xffffffffu, mx, o));
        float e = expf(x - mx);
        float sum = e;
        #pragma unroll
        for (int o = 16; o > 0; o >>= 1) sum += __shfl_xor_sync(0xffffffffu, sum, o);
        float a = e / sum;
        attn[s * B + lane] = a;
        attns_out[s * B + lane] = a;
    }
}

__global__ void build_x_kernel(const int* __restrict__ tokens_t,
                               const float* __restrict__ emb,
                               const float* __restrict__ h_prev,
                               const float* __restrict__ attn,
                               const float* __restrict__ ann,
                               float* __restrict__ Xslice) {
    int idx = blockIdx.x * blockDim.x + threadIdx.x;
    if (idx >= B * KP) return;
    int b = idx / KP;
    int e = idx % KP;
    float v = 0.f;
    if (e < EMB) {
        int tok = tokens_t[b];
        v = emb[(size_t)tok * EMB + e];
    } else if (e < EMB + H) {
        v = h_prev[b * H + (e - EMB)];
    } else if (e < KX) {
        int c = e - (EMB + H);
        float sum = 0.f;
        #pragma unroll 5
        for (int s = 0; s < S; s++)
            sum += attn[s * B + b] * ann[(size_t)(s * B + b) * A2 + c];
        v = sum;
    }
    Xslice[(size_t)b * KP + e] = v;
}

__global__ void gru_combine_kernel(const float* __restrict__ gpart,
                                   const float* __restrict__ bg,
                                   const float* __restrict__ h_old,
                                   float* __restrict__ h_new,
                                   float* __restrict__ hid_out) {
    int idx = blockIdx.x * blockDim.x + threadIdx.x;
    if (idx >= B * H) return;
    int b = idx / H, j = idx % H;
    const size_t pb = (size_t)B * 4000;
    #define GSUM(off) (gpart[(size_t)b*4000 + (off) + j] + gpart[pb + (size_t)b*4000 + (off) + j] \
                     + gpart[2*pb + (size_t)b*4000 + (off) + j] + gpart[3*pb + (size_t)b*4000 + (off) + j])
    float gr = GSUM(0)    + bg[j];
    float gz = GSUM(1000) + bg[1000 + j];
    float gi = GSUM(2000) + bg[2000 + j];
    float gh = GSUM(3000) + bg[3000 + j];
    #undef GSUM
    float r  = 1.f / (1.f + expf(-gr));
    float z  = 1.f / (1.f + expf(-gz));
    float nn = tanhf(gi + r * gh);
    float hv = (1.f - z) * nn + z * h_old[idx];
    h_new[idx] = hv;
    if (hid_out) hid_out[idx] = hv;
}

__global__ void zero_kernel(float* __restrict__ out) {
    size_t idx = (size_t)blockIdx.x * blockDim.x + threadIdx.x;
    size_t n0 = (size_t)B * V;
    if (idx < n0) out[idx] = 0.f;
    else if (idx < n0 + S * B) out[ATT_OFF + (idx - n0)] = 0.f;
}

__global__ void logsoftmax_kernel(float* __restrict__ preds_base) {
    int row = blockIdx.x;
    float* p = preds_base + (size_t)row * V;
    int tid = threadIdx.x;
    __shared__ float red[8];
    float mx = -1e30f;
    for (int i = tid; i < V; i += 256) mx = fmaxf(mx, p[i]);
    #pragma unroll
    for (int o = 16; o > 0; o >>= 1) mx = fmaxf(mx, __shfl_xor_sync(0xffffffffu, mx, o));
    if ((tid & 31) == 0) red[tid >> 5] = mx;
    __syncthreads();
    if (tid < 8) {
        float v = red[tid];
        #pragma unroll
        for (int o = 4; o > 0; o >>= 1) v = fmaxf(v, __shfl_xor_sync(0xffu, v, o));
        red[tid] = v;
    }
    __syncthreads();
    mx = red[0];
    __syncthreads();
    float sum = 0.f;
    for (int i = tid; i < V; i += 256) sum += expf(p[i] - mx);
    #pragma unroll
    for (int o = 16; o > 0; o >>= 1) sum += __shfl_xor_sync(0xffffffffu, sum, o);
    if ((tid & 31) == 0) red[tid >> 5] = sum;
    __syncthreads();
    if (tid < 8) {
        float v = red[tid];
        #pragma unroll
        for (int o = 4; o > 0; o >>= 1) v += __shfl_xor_sync(0xffu, v, o);
        red[tid] = v;
    }
    __syncthreads();
    float lse = mx + logf(red[0]);
    for (int i = tid; i < V; i += 256) p[i] = p[i] - lse;
}

// ==================== host orchestration ====================
static inline int ceil_div(int a, int b) { return (a + b - 1) / b; }

extern "C" void kernel_launch(void* const* d_in, const int* in_sizes, int n_in,
                              void* d_out, int out_size) {
    const int*   tokens = (const int*)  d_in[0];
    const float* ann    = (const float*)d_in[1];
    const float* emb    = (const float*)d_in[2];
    const float* W_h    = (const float*)d_in[3];
    const float* b_h    = (const float*)d_in[4];
    const float* W_c    = (const float*)d_in[5];
    const float* b_c    = (const float*)d_in[6];
    const float* w_a    = (const float*)d_in[7];
    const float* W_ih   = (const float*)d_in[8];
    const float* W_hh   = (const float*)d_in[9];
    const float* b_ih   = (const float*)d_in[10];
    const float* b_hh   = (const float*)d_in[11];
    const float* W_p    = (const float*)d_in[12];
    const float* b_p    = (const float*)d_in[13];
    float* out = (float*)d_out;

    float* WhT;  cudaGetSymbolAddress((void**)&WhT, g_WhT);
    float* WcT;  cudaGetSymbolAddress((void**)&WcT, g_WcT);
    uint32_t* Wph; cudaGetSymbolAddress((void**)&Wph, g_Wph);
    uint32_t* Xh;  cudaGetSymbolAddress((void**)&Xh, g_Xh);
    float* WgT;  cudaGetSymbolAddress((void**)&WgT, g_WgT);
    float* bg;   cudaGetSymbolAddress((void**)&bg,  g_bg);
    float* annproj; cudaGetSymbolAddress((void**)&annproj, g_annproj);
    float* hbuf; cudaGetSymbolAddress((void**)&hbuf, g_h);
    float* hpart; cudaGetSymbolAddress((void**)&hpart, g_hpart);
    float* attn; cudaGetSymbolAddress((void**)&attn, g_attn);
    float* Xall; cudaGetSymbolAddress((void**)&Xall, g_X);
    float* gpart; cudaGetSymbolAddress((void**)&gpart, g_gpart);

    cudaFuncSetAttribute(pred_mma_kernel,
                         cudaFuncAttributeMaxDynamicSharedMemorySize, PM_SMEM_B);

    dim3 tb(32, 8);
    transpose_kernel<<<dim3(ceil_div(ECH, 32), ceil_div(H, 32)), tb>>>(W_h, WhT, H, ECH);
    transpose_kernel<<<dim3(ceil_div(H + A2, 32), ceil_div(H, 32)), tb>>>(W_c, WcT, H, H + A2);
    {
        size_t ta = (size_t)MT_TILES * NQ * 1024;
        pack_wp_h_kernel<<<(int)((ta + 255) / 256), 256>>>(W_p, Wph);
        size_t t2 = (size_t)KX * 4000;
        build_wg_kernel<<<(int)((t2 + 255) / 256), 256>>>(W_ih, W_hh, WgT);
        build_bg_kernel<<<ceil_div(4000, 256), 256>>>(b_ih, b_hh, bg);
        size_t t3 = (size_t)B * V + S * B;
        zero_kernel<<<(int)((t3 + 255) / 256), 256>>>(out);
    }
    // h0 = tanh(ann[0,:,ECH:] @ W_h^T + b_h)
    gemm_kernel<<<dim3(ceil_div(H, 64), 1), 128>>>(
        WhT, ann + ECH, b_h, hbuf, 1LL, (long long)H, H, B, ECH, H, A2, 1);
    // annproj = ann @ W_c[:,1000:]^T + b_c
    gemm_kernel<<<dim3(ceil_div(H, 64), ceil_div(S * B, 32)), 128>>>(
        WcT + (size_t)H * H, ann, b_c, annproj, 1LL, (long long)H, H, S * B, A2, H, A2, 0);

    int cur = 0;
    for (int t = 1; t <= NSTEP; t++) {
        int st = t - 1;
        float* h_cur = hbuf + (size_t)cur * B * H;
        float* h_nxt = hbuf + (size_t)(1 - cur) * B * H;
        float* Xs = Xall + (size_t)st * B * KP;

        gemm_splitk_kernel<<<dim3(ceil_div(H, 64), 1, 4), 128>>>(
            WcT, h_cur, hpart, H, B, H, H, H, 250);
        scores_softmax_kernel<<<S, 256>>>(hpart, annproj, w_a, attn,
                                          out + ATT_OFF + (size_t)t * S * B);
        build_x_kernel<<<ceil_div(B * KP, 256), 256>>>(
            tokens + (size_t)(t - 1) * B, emb, h_cur, attn, ann, Xs);
        gemm_splitk_kernel<<<dim3(ceil_div(4000, 64), 1, 4), 128>>>(
            WgT, Xs, gpart, 4000, B, KX, 4000, KP, 905);
        gru_combine_kernel<<<ceil_div(B * H, 256), 256>>>(
            gpart, bg, h_cur, h_nxt, (t == NSTEP) ? (out + HID_OFF) : (float*)nullptr);
        cur = 1 - cur;
    }

    // pack X to fragment-major fp16, then batched prediction GEMM
    {
        size_t tx = (size_t)NT_TILES * NQ * 512;
        pack_x_h_kernel<<<(int)((tx + 255) / 256), 256>>>(Xall, Xh);
    }
    pred_mma_kernel<<<dim3(NT_TILES, MT_TILES), 256, PM_SMEM_B>>>(
        Wph, Xh, b_p, out + (size_t)B * V);
    logsoftmax_kernel<<<NPRED, 256>>>(out + (size_t)B * V);
}